// round 3
// baseline (speedup 1.0000x reference)
#include <cuda_runtime.h>
#include <cuda_bf16.h>
#include <cstdint>

// ---------------------------------------------------------------------------
// Problem constants
// ---------------------------------------------------------------------------
#define BATCH 4
#define SEQ   2048
#define CDIM  1024
#define NHEAD 16
#define HDIM  64
#define C3    (3 * CDIM)   // 3072
#define MROWS (BATCH * SEQ) // 8192

// ---------------------------------------------------------------------------
// Scratch (device globals — no runtime allocation allowed)
// ---------------------------------------------------------------------------
__device__ __align__(256) float g_qkv[(size_t)MROWS * C3];   // [B*T, 3C]
__device__ __align__(256) float g_y[(size_t)MROWS * CDIM];   // [B*T, C] attn output

// ---------------------------------------------------------------------------
// SGEMM with fused bias: C[M,N] = A[M,K] @ B[K,N] + bias[N]
// 128x128 block, BK=8, 256 threads, 8x8 per thread (split 4+4 for bank-safe LDS)
// Assumes M%128==0, N%128==0, K%8==0, all pointers 16B aligned, K,N mult of 4.
// ---------------------------------------------------------------------------
#define GBM 128
#define GBN 128
#define GBK 8

__global__ __launch_bounds__(256) void sgemm_bias(
    const float* __restrict__ A, const float* __restrict__ B,
    const float* __restrict__ bias, float* __restrict__ C,
    int M, int N, int K)
{
    __shared__ float As[GBK][GBM];
    __shared__ float Bs[GBK][GBN];

    const int tid = threadIdx.x;
    const int row0 = blockIdx.y * GBM;
    const int col0 = blockIdx.x * GBN;

    // A tile load mapping: 128 rows x 8 cols -> 256 float4 (2 per row)
    const int a_row  = tid >> 1;
    const int a_col4 = (tid & 1) * 4;
    // B tile load mapping: 8 rows x 128 cols -> 256 float4
    const int b_row  = tid >> 5;
    const int b_col4 = (tid & 31) * 4;

    const int ty4 = (tid >> 4) * 4;   // 0..60
    const int tx4 = (tid & 15) * 4;   // 0..60

    float acc[8][8];
    #pragma unroll
    for (int i = 0; i < 8; i++)
        #pragma unroll
        for (int j = 0; j < 8; j++)
            acc[i][j] = 0.f;

    const float* Aptr = A + (size_t)(row0 + a_row) * K + a_col4;
    const float* Bptr = B + (size_t)b_row * N + col0 + b_col4;

    for (int k0 = 0; k0 < K; k0 += GBK) {
        float4 av = *(const float4*)(Aptr + k0);
        float4 bv = *(const float4*)(Bptr + (size_t)k0 * N);

        // transpose-store A fragment
        As[a_col4 + 0][a_row] = av.x;
        As[a_col4 + 1][a_row] = av.y;
        As[a_col4 + 2][a_row] = av.z;
        As[a_col4 + 3][a_row] = av.w;
        *(float4*)&Bs[b_row][b_col4] = bv;
        __syncthreads();

        #pragma unroll
        for (int k = 0; k < GBK; k++) {
            float4 a0 = *(const float4*)&As[k][ty4];
            float4 a1 = *(const float4*)&As[k][ty4 + 64];
            float4 b0 = *(const float4*)&Bs[k][tx4];
            float4 b1 = *(const float4*)&Bs[k][tx4 + 64];
            float a[8] = {a0.x, a0.y, a0.z, a0.w, a1.x, a1.y, a1.z, a1.w};
            float b[8] = {b0.x, b0.y, b0.z, b0.w, b1.x, b1.y, b1.z, b1.w};
            #pragma unroll
            for (int i = 0; i < 8; i++)
                #pragma unroll
                for (int j = 0; j < 8; j++)
                    acc[i][j] += a[i] * b[j];
        }
        __syncthreads();
    }

    // epilogue: bias + store (two float4 column groups per row)
    float4 bias0 = *(const float4*)(bias + col0 + tx4);
    float4 bias1 = *(const float4*)(bias + col0 + tx4 + 64);
    #pragma unroll
    for (int i = 0; i < 8; i++) {
        int r = row0 + ((i < 4) ? (ty4 + i) : (64 + ty4 + i - 4));
        float* crow = C + (size_t)r * N + col0;
        float4 v0, v1;
        v0.x = acc[i][0] + bias0.x; v0.y = acc[i][1] + bias0.y;
        v0.z = acc[i][2] + bias0.z; v0.w = acc[i][3] + bias0.w;
        v1.x = acc[i][4] + bias1.x; v1.y = acc[i][5] + bias1.y;
        v1.z = acc[i][6] + bias1.z; v1.w = acc[i][7] + bias1.w;
        *(float4*)(crow + tx4)      = v0;
        *(float4*)(crow + tx4 + 64) = v1;
    }
}

// ---------------------------------------------------------------------------
// Flash attention (fp32, causal). One thread = one query row.
// Block: 128 threads = 128 query rows. grid = (T/128, H, B).
// q (pre-scaled) and o accumulator in registers; K/V tiles of 16 keys in SMEM.
// Online softmax with per-chunk rescale.
// ---------------------------------------------------------------------------
#define FA_BM 128
#define FA_BK 16

__global__ __launch_bounds__(128) void flash_attn(
    const float* __restrict__ qkv, float* __restrict__ y)
{
    const int qt  = blockIdx.x;
    const int h   = blockIdx.y;
    const int b   = blockIdx.z;
    const int tid = threadIdx.x;
    const int qi  = qt * FA_BM + tid;

    __shared__ float Ks[FA_BK][HDIM];
    __shared__ float Vs[FA_BK][HDIM];

    // load & pre-scale q row (1/sqrt(64) = 0.125)
    float q[HDIM];
    {
        const float* qrow = qkv + ((size_t)(b * SEQ + qi)) * C3 + h * HDIM;
        #pragma unroll
        for (int d = 0; d < HDIM; d += 4) {
            float4 v = *(const float4*)(qrow + d);
            q[d + 0] = v.x * 0.125f;
            q[d + 1] = v.y * 0.125f;
            q[d + 2] = v.z * 0.125f;
            q[d + 3] = v.w * 0.125f;
        }
    }

    float o[HDIM];
    #pragma unroll
    for (int d = 0; d < HDIM; d++) o[d] = 0.f;
    float m = -1e30f, l = 0.f;

    const int kend = qt * FA_BM + FA_BM;   // keys 0..kend-1 (multiple of FA_BK)

    for (int k0 = 0; k0 < kend; k0 += FA_BK) {
        // cooperative tile load: 16 rows x 16 float4 per tensor, 2 f4/thread each
        __syncthreads();
        #pragma unroll
        for (int i = 0; i < 2; i++) {
            int idx = tid + i * 128;
            int r = idx >> 4;
            int c = (idx & 15) << 2;
            const float* kp = qkv + ((size_t)(b * SEQ + k0 + r)) * C3
                              + CDIM + h * HDIM + c;
            *(float4*)&Ks[r][c] = *(const float4*)kp;
            *(float4*)&Vs[r][c] = *(const float4*)(kp + CDIM);
        }
        __syncthreads();

        // scores for this chunk
        float s[FA_BK];
        #pragma unroll
        for (int j = 0; j < FA_BK; j++) {
            const float4* kr = (const float4*)Ks[j];
            float acc = 0.f;
            #pragma unroll
            for (int d4 = 0; d4 < 16; d4++) {
                float4 kv = kr[d4];
                acc += q[4 * d4 + 0] * kv.x;
                acc += q[4 * d4 + 1] * kv.y;
                acc += q[4 * d4 + 2] * kv.z;
                acc += q[4 * d4 + 3] * kv.w;
            }
            s[j] = ((k0 + j) <= qi) ? acc : -1e30f;
        }

        // online softmax update (one rescale per chunk)
        float cmax = s[0];
        #pragma unroll
        for (int j = 1; j < FA_BK; j++) cmax = fmaxf(cmax, s[j]);
        float newm = fmaxf(m, cmax);
        float corr = __expf(m - newm);
        l *= corr;
        #pragma unroll
        for (int d = 0; d < HDIM; d++) o[d] *= corr;

        #pragma unroll
        for (int j = 0; j < FA_BK; j++) {
            float p = __expf(s[j] - newm);
            l += p;
            const float4* vr = (const float4*)Vs[j];
            #pragma unroll
            for (int d4 = 0; d4 < 16; d4++) {
                float4 vv = vr[d4];
                o[4 * d4 + 0] += p * vv.x;
                o[4 * d4 + 1] += p * vv.y;
                o[4 * d4 + 2] += p * vv.z;
                o[4 * d4 + 3] += p * vv.w;
            }
        }
        m = newm;
    }

    // normalize + write
    float inv = 1.f / l;
    float* yrow = y + ((size_t)(b * SEQ + qi)) * CDIM + h * HDIM;
    #pragma unroll
    for (int d = 0; d < HDIM; d += 4) {
        float4 v;
        v.x = o[d + 0] * inv; v.y = o[d + 1] * inv;
        v.z = o[d + 2] * inv; v.w = o[d + 3] * inv;
        *(float4*)(yrow + d) = v;
    }
}

// ---------------------------------------------------------------------------
// Launch
// ---------------------------------------------------------------------------
extern "C" void kernel_launch(void* const* d_in, const int* in_sizes, int n_in,
                              void* d_out, int out_size)
{
    const float* x      = (const float*)d_in[0];
    const float* W_attn = (const float*)d_in[1];
    const float* b_attn = (const float*)d_in[2];
    const float* W_proj = (const float*)d_in[3];
    const float* b_proj = (const float*)d_in[4];
    float* out = (float*)d_out;

    float *qkv_ptr, *y_ptr;
    cudaGetSymbolAddress((void**)&qkv_ptr, g_qkv);
    cudaGetSymbolAddress((void**)&y_ptr,   g_y);

    // 1) qkv = x @ W_attn + b_attn   [8192,1024]x[1024,3072]
    {
        dim3 grid(C3 / GBN, MROWS / GBM);
        sgemm_bias<<<grid, 256>>>(x, W_attn, b_attn, qkv_ptr,
                                  MROWS, C3, CDIM);
    }
    // 2) flash attention -> g_y
    {
        dim3 grid(SEQ / FA_BM, NHEAD, BATCH);
        flash_attn<<<grid, 128>>>(qkv_ptr, y_ptr);
    }
    // 3) out = y @ W_proj + b_proj   [8192,1024]x[1024,1024]
    {
        dim3 grid(CDIM / GBN, MROWS / GBM);
        sgemm_bias<<<grid, 256>>>(y_ptr, W_proj, b_proj, out,
                                  MROWS, CDIM, CDIM);
    }
}

// round 6
// speedup vs baseline: 1.4348x; 1.4348x over previous
#include <cuda_runtime.h>
#include <cuda_bf16.h>
#include <cstdint>

// ---------------------------------------------------------------------------
// Problem constants
// ---------------------------------------------------------------------------
#define BATCH 4
#define SEQ   2048
#define CDIM  1024
#define NHEAD 16
#define HDIM  64
#define C3    (3 * CDIM)   // 3072
#define MROWS (BATCH * SEQ) // 8192

// ---------------------------------------------------------------------------
// Scratch (device globals — no runtime allocation allowed)
// ---------------------------------------------------------------------------
__device__ __align__(256) float g_qkv[(size_t)MROWS * C3];   // [B*T, 3C]
__device__ __align__(256) float g_y[(size_t)MROWS * CDIM];   // [B*T, C] attn output

// ---------------------------------------------------------------------------
// TF32 tensor-core GEMM with fused bias: C[M,N] = A[M,K] @ B[K,N] + bias[N]
// 128x128x32 tile, 256 threads (8 warps in 2x4), warp tile 64x32,
// mma.sync.m16n8k8 tf32, cp.async double-buffered smem.
// Requires M%128==0, N%128==0, K%32==0.
// ---------------------------------------------------------------------------
#define TBM 128
#define TBN 128
#define TBK 32
#define LDA 36     // A smem row stride (floats): 36 % 32 == 4 -> conflict-free frags
#define LDB 136    // B smem row stride (floats): 136 % 32 == 8 -> conflict-free frags
#define A_BUF (TBM * LDA)         // 4608 floats
#define B_BUF (TBK * LDB)         // 4352 floats
#define GEMM_SMEM_BYTES ((2 * A_BUF + 2 * B_BUF) * 4)   // 71680 B

__device__ __forceinline__ uint32_t f2tf32(float x) {
    uint32_t r;
    asm("cvt.rna.tf32.f32 %0, %1;" : "=r"(r) : "f"(x));
    return r;
}

__device__ __forceinline__ void mma_tf32(float c[4], const uint32_t a[4],
                                         const uint32_t b[2]) {
    asm volatile(
        "mma.sync.aligned.m16n8k8.row.col.f32.tf32.tf32.f32 "
        "{%0,%1,%2,%3}, {%4,%5,%6,%7}, {%8,%9}, {%0,%1,%2,%3};"
        : "+f"(c[0]), "+f"(c[1]), "+f"(c[2]), "+f"(c[3])
        : "r"(a[0]), "r"(a[1]), "r"(a[2]), "r"(a[3]), "r"(b[0]), "r"(b[1]));
}

__device__ __forceinline__ void cp_async16(float* smem_dst, const float* gmem_src) {
    uint32_t s = (uint32_t)__cvta_generic_to_shared(smem_dst);
    asm volatile("cp.async.cg.shared.global [%0], [%1], 16;\n" ::"r"(s), "l"(gmem_src));
}
#define CP_COMMIT()  asm volatile("cp.async.commit_group;\n")
#define CP_WAIT(n)   asm volatile("cp.async.wait_group %0;\n" ::"n"(n))

__global__ __launch_bounds__(256, 2) void gemm_tf32_bias(
    const float* __restrict__ A, const float* __restrict__ B,
    const float* __restrict__ bias, float* __restrict__ C,
    int M, int N, int K)
{
    extern __shared__ float smem[];
    float* As = smem;                 // 2 * A_BUF
    float* Bs = smem + 2 * A_BUF;     // 2 * B_BUF

    const int tid  = threadIdx.x;
    const int lane = tid & 31;
    const int w    = tid >> 5;
    const int g    = lane >> 2;       // groupID 0..7
    const int t    = lane & 3;        // thread-in-group 0..3
    const int wm   = w >> 2;          // 0..1
    const int wn   = w & 3;           // 0..3
    const int m_base = wm * 64;
    const int n_base = wn * 32;

    const int row0 = blockIdx.y * TBM;
    const int col0 = blockIdx.x * TBN;

    float acc[4][4][4];
    #pragma unroll
    for (int mi = 0; mi < 4; mi++)
        #pragma unroll
        for (int ni = 0; ni < 4; ni++)
            #pragma unroll
            for (int r = 0; r < 4; r++)
                acc[mi][ni][r] = 0.f;

    // tile-load thread mapping (4 float4 chunks per thread per matrix)
    // A: 128 rows x 8 f4/row;  B: 32 rows x 32 f4/row
    const int nt = K / TBK;

    auto load_tile = [&](int kt, int buf) {
        float* Ad = As + buf * A_BUF;
        float* Bd = Bs + buf * B_BUF;
        #pragma unroll
        for (int i = 0; i < 4; i++) {
            int idx = tid + i * 256;
            int ar  = idx >> 3;
            int ac4 = (idx & 7) << 2;
            cp_async16(Ad + ar * LDA + ac4,
                       A + (size_t)(row0 + ar) * K + kt + ac4);
            int br  = idx >> 5;
            int bc4 = (idx & 31) << 2;
            cp_async16(Bd + br * LDB + bc4,
                       B + (size_t)(kt + br) * N + col0 + bc4);
        }
        CP_COMMIT();
    };

    load_tile(0, 0);

    int buf = 0;
    for (int tix = 0; tix < nt; tix++) {
        if (tix + 1 < nt) {
            load_tile((tix + 1) * TBK, buf ^ 1);
            CP_WAIT(1);
        } else {
            CP_WAIT(0);
        }
        __syncthreads();

        const float* Ad = As + buf * A_BUF;
        const float* Bd = Bs + buf * B_BUF;

        #pragma unroll
        for (int ks = 0; ks < 4; ks++) {
            const int k0 = ks * 8;
            uint32_t af[4][4], bf[4][2];
            #pragma unroll
            for (int mi = 0; mi < 4; mi++) {
                int ra = m_base + mi * 16 + g;
                af[mi][0] = f2tf32(Ad[ra * LDA + k0 + t]);
                af[mi][1] = f2tf32(Ad[(ra + 8) * LDA + k0 + t]);
                af[mi][2] = f2tf32(Ad[ra * LDA + k0 + t + 4]);
                af[mi][3] = f2tf32(Ad[(ra + 8) * LDA + k0 + t + 4]);
            }
            #pragma unroll
            for (int ni = 0; ni < 4; ni++) {
                int cb = n_base + ni * 8 + g;
                bf[ni][0] = f2tf32(Bd[(k0 + t) * LDB + cb]);
                bf[ni][1] = f2tf32(Bd[(k0 + t + 4) * LDB + cb]);
            }
            #pragma unroll
            for (int mi = 0; mi < 4; mi++)
                #pragma unroll
                for (int ni = 0; ni < 4; ni++)
                    mma_tf32(acc[mi][ni], af[mi], bf[ni]);
        }
        __syncthreads();
        buf ^= 1;
    }

    // epilogue: bias + store. c0,c1 -> (row, 2t..2t+1); c2,c3 -> (row+8, ...)
    #pragma unroll
    for (int ni = 0; ni < 4; ni++) {
        int cc = col0 + n_base + ni * 8 + 2 * t;
        float2 bb = *(const float2*)&bias[cc];
        #pragma unroll
        for (int mi = 0; mi < 4; mi++) {
            int rr = row0 + m_base + mi * 16 + g;
            float2 v0, v1;
            v0.x = acc[mi][ni][0] + bb.x;
            v0.y = acc[mi][ni][1] + bb.y;
            v1.x = acc[mi][ni][2] + bb.x;
            v1.y = acc[mi][ni][3] + bb.y;
            *(float2*)&C[(size_t)rr * N + cc]       = v0;
            *(float2*)&C[(size_t)(rr + 8) * N + cc] = v1;
        }
    }
}

// ---------------------------------------------------------------------------
// Flash attention (fp32, causal). One thread = one query row. (unchanged R0)
// ---------------------------------------------------------------------------
#define FA_BM 128
#define FA_BK 16

__global__ __launch_bounds__(128) void flash_attn(
    const float* __restrict__ qkv, float* __restrict__ y)
{
    const int qt  = blockIdx.x;
    const int h   = blockIdx.y;
    const int b   = blockIdx.z;
    const int tid = threadIdx.x;
    const int qi  = qt * FA_BM + tid;

    __shared__ float Ks[FA_BK][HDIM];
    __shared__ float Vs[FA_BK][HDIM];

    float q[HDIM];
    {
        const float* qrow = qkv + ((size_t)(b * SEQ + qi)) * C3 + h * HDIM;
        #pragma unroll
        for (int d = 0; d < HDIM; d += 4) {
            float4 v = *(const float4*)(qrow + d);
            q[d + 0] = v.x * 0.125f;
            q[d + 1] = v.y * 0.125f;
            q[d + 2] = v.z * 0.125f;
            q[d + 3] = v.w * 0.125f;
        }
    }

    float o[HDIM];
    #pragma unroll
    for (int d = 0; d < HDIM; d++) o[d] = 0.f;
    float m = -1e30f, l = 0.f;

    const int kend = qt * FA_BM + FA_BM;

    for (int k0 = 0; k0 < kend; k0 += FA_BK) {
        __syncthreads();
        #pragma unroll
        for (int i = 0; i < 2; i++) {
            int idx = tid + i * 128;
            int r = idx >> 4;
            int c = (idx & 15) << 2;
            const float* kp = qkv + ((size_t)(b * SEQ + k0 + r)) * C3
                              + CDIM + h * HDIM + c;
            *(float4*)&Ks[r][c] = *(const float4*)kp;
            *(float4*)&Vs[r][c] = *(const float4*)(kp + CDIM);
        }
        __syncthreads();

        float s[FA_BK];
        #pragma unroll
        for (int j = 0; j < FA_BK; j++) {
            const float4* kr = (const float4*)Ks[j];
            float acc = 0.f;
            #pragma unroll
            for (int d4 = 0; d4 < 16; d4++) {
                float4 kv = kr[d4];
                acc += q[4 * d4 + 0] * kv.x;
                acc += q[4 * d4 + 1] * kv.y;
                acc += q[4 * d4 + 2] * kv.z;
                acc += q[4 * d4 + 3] * kv.w;
            }
            s[j] = ((k0 + j) <= qi) ? acc : -1e30f;
        }

        float cmax = s[0];
        #pragma unroll
        for (int j = 1; j < FA_BK; j++) cmax = fmaxf(cmax, s[j]);
        float newm = fmaxf(m, cmax);
        float corr = __expf(m - newm);
        l *= corr;
        #pragma unroll
        for (int d = 0; d < HDIM; d++) o[d] *= corr;

        #pragma unroll
        for (int j = 0; j < FA_BK; j++) {
            float p = __expf(s[j] - newm);
            l += p;
            const float4* vr = (const float4*)Vs[j];
            #pragma unroll
            for (int d4 = 0; d4 < 16; d4++) {
                float4 vv = vr[d4];
                o[4 * d4 + 0] += p * vv.x;
                o[4 * d4 + 1] += p * vv.y;
                o[4 * d4 + 2] += p * vv.z;
                o[4 * d4 + 3] += p * vv.w;
            }
        }
        m = newm;
    }

    float inv = 1.f / l;
    float* yrow = y + ((size_t)(b * SEQ + qi)) * CDIM + h * HDIM;
    #pragma unroll
    for (int d = 0; d < HDIM; d += 4) {
        float4 v;
        v.x = o[d + 0] * inv; v.y = o[d + 1] * inv;
        v.z = o[d + 2] * inv; v.w = o[d + 3] * inv;
        *(float4*)(yrow + d) = v;
    }
}

// ---------------------------------------------------------------------------
// Launch
// ---------------------------------------------------------------------------
extern "C" void kernel_launch(void* const* d_in, const int* in_sizes, int n_in,
                              void* d_out, int out_size)
{
    const float* x      = (const float*)d_in[0];
    const float* W_attn = (const float*)d_in[1];
    const float* b_attn = (const float*)d_in[2];
    const float* W_proj = (const float*)d_in[3];
    const float* b_proj = (const float*)d_in[4];
    float* out = (float*)d_out;

    float *qkv_ptr, *y_ptr;
    cudaGetSymbolAddress((void**)&qkv_ptr, g_qkv);
    cudaGetSymbolAddress((void**)&y_ptr,   g_y);

    cudaFuncSetAttribute(gemm_tf32_bias,
                         cudaFuncAttributeMaxDynamicSharedMemorySize,
                         GEMM_SMEM_BYTES);

    // 1) qkv = x @ W_attn + b_attn   [8192,1024]x[1024,3072]
    {
        dim3 grid(C3 / TBN, MROWS / TBM);
        gemm_tf32_bias<<<grid, 256, GEMM_SMEM_BYTES>>>(
            x, W_attn, b_attn, qkv_ptr, MROWS, C3, CDIM);
    }
    // 2) flash attention -> g_y
    {
        dim3 grid(SEQ / FA_BM, NHEAD, BATCH);
        flash_attn<<<grid, 128>>>(qkv_ptr, y_ptr);
    }
    // 3) out = y @ W_proj + b_proj   [8192,1024]x[1024,1024]
    {
        dim3 grid(CDIM / TBN, MROWS / TBM);
        gemm_tf32_bias<<<grid, 256, GEMM_SMEM_BYTES>>>(
            y_ptr, W_proj, b_proj, out, MROWS, CDIM, CDIM);
    }
}

// round 8
// speedup vs baseline: 3.8503x; 2.6835x over previous
#include <cuda_runtime.h>
#include <cuda_bf16.h>
#include <cstdint>

// ---------------------------------------------------------------------------
// Problem constants
// ---------------------------------------------------------------------------
#define BATCH 4
#define SEQ   2048
#define CDIM  1024
#define NHEAD 16
#define HDIM  64
#define C3    (3 * CDIM)   // 3072
#define MROWS (BATCH * SEQ) // 8192

// ---------------------------------------------------------------------------
// Scratch (device globals — no runtime allocation allowed)
// ---------------------------------------------------------------------------
__device__ __align__(256) float g_qkv[(size_t)MROWS * C3];   // [B*T, 3C]
__device__ __align__(256) float g_y[(size_t)MROWS * CDIM];   // [B*T, C] attn output

// ---------------------------------------------------------------------------
// Common PTX helpers
// ---------------------------------------------------------------------------
__device__ __forceinline__ uint32_t f2tf32(float x) {
    uint32_t r;
    asm("cvt.rna.tf32.f32 %0, %1;" : "=r"(r) : "f"(x));
    return r;
}

__device__ __forceinline__ void mma_tf32(float c[4], const uint32_t a[4],
                                         const uint32_t b[2]) {
    asm volatile(
        "mma.sync.aligned.m16n8k8.row.col.f32.tf32.tf32.f32 "
        "{%0,%1,%2,%3}, {%4,%5,%6,%7}, {%8,%9}, {%0,%1,%2,%3};"
        : "+f"(c[0]), "+f"(c[1]), "+f"(c[2]), "+f"(c[3])
        : "r"(a[0]), "r"(a[1]), "r"(a[2]), "r"(a[3]), "r"(b[0]), "r"(b[1]));
}

__device__ __forceinline__ void cp_async16(float* smem_dst, const float* gmem_src) {
    uint32_t s = (uint32_t)__cvta_generic_to_shared(smem_dst);
    asm volatile("cp.async.cg.shared.global [%0], [%1], 16;\n" ::"r"(s), "l"(gmem_src));
}
#define CP_COMMIT()  asm volatile("cp.async.commit_group;\n")
#define CP_WAIT(n)   asm volatile("cp.async.wait_group %0;\n" ::"n"(n))

// ---------------------------------------------------------------------------
// TF32 tensor-core GEMM with fused bias (unchanged from R3)
// ---------------------------------------------------------------------------
#define TBM 128
#define TBN 128
#define TBK 32
#define LDA 36
#define LDB 136
#define A_BUF (TBM * LDA)
#define B_BUF (TBK * LDB)
#define GEMM_SMEM_BYTES ((2 * A_BUF + 2 * B_BUF) * 4)

__global__ __launch_bounds__(256, 2) void gemm_tf32_bias(
    const float* __restrict__ A, const float* __restrict__ B,
    const float* __restrict__ bias, float* __restrict__ C,
    int M, int N, int K)
{
    extern __shared__ float smem[];
    float* As = smem;
    float* Bs = smem + 2 * A_BUF;

    const int tid  = threadIdx.x;
    const int lane = tid & 31;
    const int w    = tid >> 5;
    const int g    = lane >> 2;
    const int t    = lane & 3;
    const int wm   = w >> 2;
    const int wn   = w & 3;
    const int m_base = wm * 64;
    const int n_base = wn * 32;

    const int row0 = blockIdx.y * TBM;
    const int col0 = blockIdx.x * TBN;

    float acc[4][4][4];
    #pragma unroll
    for (int mi = 0; mi < 4; mi++)
        #pragma unroll
        for (int ni = 0; ni < 4; ni++)
            #pragma unroll
            for (int r = 0; r < 4; r++)
                acc[mi][ni][r] = 0.f;

    const int nt = K / TBK;

    auto load_tile = [&](int kt, int buf) {
        float* Ad = As + buf * A_BUF;
        float* Bd = Bs + buf * B_BUF;
        #pragma unroll
        for (int i = 0; i < 4; i++) {
            int idx = tid + i * 256;
            int ar  = idx >> 3;
            int ac4 = (idx & 7) << 2;
            cp_async16(Ad + ar * LDA + ac4,
                       A + (size_t)(row0 + ar) * K + kt + ac4);
            int br  = idx >> 5;
            int bc4 = (idx & 31) << 2;
            cp_async16(Bd + br * LDB + bc4,
                       B + (size_t)(kt + br) * N + col0 + bc4);
        }
        CP_COMMIT();
    };

    load_tile(0, 0);

    int buf = 0;
    for (int tix = 0; tix < nt; tix++) {
        if (tix + 1 < nt) {
            load_tile((tix + 1) * TBK, buf ^ 1);
            CP_WAIT(1);
        } else {
            CP_WAIT(0);
        }
        __syncthreads();

        const float* Ad = As + buf * A_BUF;
        const float* Bd = Bs + buf * B_BUF;

        #pragma unroll
        for (int ks = 0; ks < 4; ks++) {
            const int k0 = ks * 8;
            uint32_t af[4][4], bf[4][2];
            #pragma unroll
            for (int mi = 0; mi < 4; mi++) {
                int ra = m_base + mi * 16 + g;
                af[mi][0] = f2tf32(Ad[ra * LDA + k0 + t]);
                af[mi][1] = f2tf32(Ad[(ra + 8) * LDA + k0 + t]);
                af[mi][2] = f2tf32(Ad[ra * LDA + k0 + t + 4]);
                af[mi][3] = f2tf32(Ad[(ra + 8) * LDA + k0 + t + 4]);
            }
            #pragma unroll
            for (int ni = 0; ni < 4; ni++) {
                int cb = n_base + ni * 8 + g;
                bf[ni][0] = f2tf32(Bd[(k0 + t) * LDB + cb]);
                bf[ni][1] = f2tf32(Bd[(k0 + t + 4) * LDB + cb]);
            }
            #pragma unroll
            for (int mi = 0; mi < 4; mi++)
                #pragma unroll
                for (int ni = 0; ni < 4; ni++)
                    mma_tf32(acc[mi][ni], af[mi], bf[ni]);
        }
        __syncthreads();
        buf ^= 1;
    }

    #pragma unroll
    for (int ni = 0; ni < 4; ni++) {
        int cc = col0 + n_base + ni * 8 + 2 * t;
        float2 bb = *(const float2*)&bias[cc];
        #pragma unroll
        for (int mi = 0; mi < 4; mi++) {
            int rr = row0 + m_base + mi * 16 + g;
            float2 v0, v1;
            v0.x = acc[mi][ni][0] + bb.x;
            v0.y = acc[mi][ni][1] + bb.y;
            v1.x = acc[mi][ni][2] + bb.x;
            v1.y = acc[mi][ni][3] + bb.y;
            *(float2*)&C[(size_t)rr * N + cc]       = v0;
            *(float2*)&C[(size_t)(rr + 8) * N + cc] = v1;
        }
    }
}

// ---------------------------------------------------------------------------
// Tensor-core flash attention (tf32 mma, causal, FA2-style).
// Block: 128 threads (4 warps), 64 queries per block, one (b,h) per block.z/y.
// Each warp owns 16 query rows: Q frags + O accumulators register-resident.
// K/V tiles of 64 keys double-buffered in smem via cp.async.
// ---------------------------------------------------------------------------
#define FA_BM 64
#define FA_BN 64
#define LDK 68   // bank: 4g+t  -> conflict-free K fragments
#define LDV 72   // bank: 8t+g  -> conflict-free V fragments
#define LDP 68   // bank: 4g+t  -> conflict-free P fragments
#define FA_SMEM_BYTES ((2 * FA_BN * LDK + 2 * FA_BN * LDV + FA_BM * LDP) * 4)

__global__ __launch_bounds__(128) void flash_attn_tc(
    const float* __restrict__ qkv, float* __restrict__ y)
{
    extern __shared__ float fsm[];
    float* KsB = fsm;                                   // [2][FA_BN*LDK]
    float* VsB = fsm + 2 * FA_BN * LDK;                 // [2][FA_BN*LDV]
    float* Ps  = fsm + 2 * FA_BN * LDK + 2 * FA_BN * LDV; // [FA_BM*LDP]

    const int qt   = blockIdx.x;
    const int h    = blockIdx.y;
    const int b    = blockIdx.z;
    const int tid  = threadIdx.x;
    const int lane = tid & 31;
    const int w    = tid >> 5;
    const int g    = lane >> 2;
    const int t    = lane & 3;
    const int q0   = qt * FA_BM;

    const float* kbase = qkv + (size_t)b * SEQ * C3 + CDIM + h * HDIM;
    const float* vbase = kbase + CDIM;

    auto load_kv = [&](int k0, int bufi) {
        float* Kd = KsB + bufi * FA_BN * LDK;
        float* Vd = VsB + bufi * FA_BN * LDV;
        #pragma unroll
        for (int i = 0; i < 8; i++) {
            int idx = tid + i * 128;
            int r  = idx >> 4;
            int c4 = (idx & 15) << 2;
            const float* src = kbase + (size_t)(k0 + r) * C3 + c4;
            cp_async16(Kd + r * LDK + c4, src);
            cp_async16(Vd + r * LDV + c4, vbase + (size_t)(k0 + r) * C3 + c4);
        }
        CP_COMMIT();
    };

    load_kv(0, 0);

    // Q fragments for this warp's 16 rows (pre-scaled by 1/sqrt(64))
    uint32_t qf[8][4];
    {
        const float* qr0 = qkv + (size_t)(b * SEQ + q0 + w * 16 + g) * C3 + h * HDIM;
        const float* qr1 = qr0 + (size_t)8 * C3;
        #pragma unroll
        for (int kc = 0; kc < 8; kc++) {
            qf[kc][0] = f2tf32(qr0[kc * 8 + t]     * 0.125f);
            qf[kc][1] = f2tf32(qr1[kc * 8 + t]     * 0.125f);
            qf[kc][2] = f2tf32(qr0[kc * 8 + t + 4] * 0.125f);
            qf[kc][3] = f2tf32(qr1[kc * 8 + t + 4] * 0.125f);
        }
    }

    float oacc[8][4];
    #pragma unroll
    for (int nt = 0; nt < 8; nt++)
        #pragma unroll
        for (int r = 0; r < 4; r++)
            oacc[nt][r] = 0.f;

    float m0 = -1e30f, m1 = -1e30f, l0 = 0.f, l1 = 0.f;
    const int rl0 = w * 16 + g;      // local query row for c0/c1
    const int rl1 = rl0 + 8;         // local query row for c2/c3

    int buf = 0;
    for (int kt = 0; kt <= qt; kt++) {
        if (kt < qt) { load_kv((kt + 1) * FA_BN, buf ^ 1); CP_WAIT(1); }
        else         { CP_WAIT(0); }
        __syncthreads();

        const float* Kd = KsB + buf * FA_BN * LDK;
        const float* Vd = VsB + buf * FA_BN * LDV;

        // ---- S = Q @ K^T ----
        float sacc[8][4];
        #pragma unroll
        for (int nt = 0; nt < 8; nt++)
            #pragma unroll
            for (int r = 0; r < 4; r++)
                sacc[nt][r] = 0.f;

        #pragma unroll
        for (int kc = 0; kc < 8; kc++) {
            #pragma unroll
            for (int nt = 0; nt < 8; nt++) {
                uint32_t bf[2];
                const float* kr = Kd + (nt * 8 + g) * LDK + kc * 8;
                bf[0] = f2tf32(kr[t]);
                bf[1] = f2tf32(kr[t + 4]);
                mma_tf32(sacc[nt], qf[kc], bf);
            }
        }

        // ---- causal mask (diagonal tile only) ----
        if (kt == qt) {
            #pragma unroll
            for (int nt = 0; nt < 8; nt++) {
                int c0 = nt * 8 + 2 * t;
                if (c0     > rl0) sacc[nt][0] = -1e30f;
                if (c0 + 1 > rl0) sacc[nt][1] = -1e30f;
                if (c0     > rl1) sacc[nt][2] = -1e30f;
                if (c0 + 1 > rl1) sacc[nt][3] = -1e30f;
            }
        }

        // ---- online softmax ----
        float mx0 = -1e30f, mx1 = -1e30f;
        #pragma unroll
        for (int nt = 0; nt < 8; nt++) {
            mx0 = fmaxf(mx0, fmaxf(sacc[nt][0], sacc[nt][1]));
            mx1 = fmaxf(mx1, fmaxf(sacc[nt][2], sacc[nt][3]));
        }
        mx0 = fmaxf(mx0, __shfl_xor_sync(0xffffffffu, mx0, 1));
        mx0 = fmaxf(mx0, __shfl_xor_sync(0xffffffffu, mx0, 2));
        mx1 = fmaxf(mx1, __shfl_xor_sync(0xffffffffu, mx1, 1));
        mx1 = fmaxf(mx1, __shfl_xor_sync(0xffffffffu, mx1, 2));

        float nm0 = fmaxf(m0, mx0), nm1 = fmaxf(m1, mx1);
        float cf0 = __expf(m0 - nm0), cf1 = __expf(m1 - nm1);
        m0 = nm0; m1 = nm1;
        l0 *= cf0; l1 *= cf1;

        float* p0row = Ps + (size_t)(w * 16 + g) * LDP;
        float* p1row = p0row + (size_t)8 * LDP;
        #pragma unroll
        for (int nt = 0; nt < 8; nt++) {
            float p0 = __expf(sacc[nt][0] - nm0);
            float p1 = __expf(sacc[nt][1] - nm0);
            float p2 = __expf(sacc[nt][2] - nm1);
            float p3 = __expf(sacc[nt][3] - nm1);
            l0 += p0 + p1;
            l1 += p2 + p3;
            oacc[nt][0] *= cf0; oacc[nt][1] *= cf0;
            oacc[nt][2] *= cf1; oacc[nt][3] *= cf1;
            uint2 u0; u0.x = f2tf32(p0); u0.y = f2tf32(p1);
            uint2 u1; u1.x = f2tf32(p2); u1.y = f2tf32(p3);
            *(uint2*)(p0row + nt * 8 + 2 * t) = u0;
            *(uint2*)(p1row + nt * 8 + 2 * t) = u1;
        }
        __syncwarp();

        // ---- O += P @ V ----
        const uint32_t* Pw = (const uint32_t*)(Ps + (size_t)(w * 16) * LDP);
        #pragma unroll
        for (int kc = 0; kc < 8; kc++) {
            uint32_t af[4];
            af[0] = Pw[(size_t)g * LDP + kc * 8 + t];
            af[1] = Pw[(size_t)(g + 8) * LDP + kc * 8 + t];
            af[2] = Pw[(size_t)g * LDP + kc * 8 + t + 4];
            af[3] = Pw[(size_t)(g + 8) * LDP + kc * 8 + t + 4];
            #pragma unroll
            for (int nt = 0; nt < 8; nt++) {
                uint32_t bf[2];
                const float* vr = Vd + (kc * 8 + t) * LDV + nt * 8 + g;
                bf[0] = f2tf32(vr[0]);
                bf[1] = f2tf32(vr[4 * LDV]);
                mma_tf32(oacc[nt], af, bf);
            }
        }
        __syncthreads();
        buf ^= 1;
    }

    // ---- epilogue: reduce l across quad, normalize, store ----
    l0 += __shfl_xor_sync(0xffffffffu, l0, 1);
    l0 += __shfl_xor_sync(0xffffffffu, l0, 2);
    l1 += __shfl_xor_sync(0xffffffffu, l1, 1);
    l1 += __shfl_xor_sync(0xffffffffu, l1, 2);
    float inv0 = 1.f / l0, inv1 = 1.f / l1;

    const int row0g = q0 + rl0;
    float* y0 = y + (size_t)(b * SEQ + row0g) * CDIM + h * HDIM;
    float* y1 = y0 + (size_t)8 * CDIM;
    #pragma unroll
    for (int nt = 0; nt < 8; nt++) {
        int cc = nt * 8 + 2 * t;
        float2 v0, v1;
        v0.x = oacc[nt][0] * inv0; v0.y = oacc[nt][1] * inv0;
        v1.x = oacc[nt][2] * inv1; v1.y = oacc[nt][3] * inv1;
        *(float2*)(y0 + cc) = v0;
        *(float2*)(y1 + cc) = v1;
    }
}

// ---------------------------------------------------------------------------
// Launch
// ---------------------------------------------------------------------------
extern "C" void kernel_launch(void* const* d_in, const int* in_sizes, int n_in,
                              void* d_out, int out_size)
{
    const float* x      = (const float*)d_in[0];
    const float* W_attn = (const float*)d_in[1];
    const float* b_attn = (const float*)d_in[2];
    const float* W_proj = (const float*)d_in[3];
    const float* b_proj = (const float*)d_in[4];
    float* out = (float*)d_out;

    float *qkv_ptr, *y_ptr;
    cudaGetSymbolAddress((void**)&qkv_ptr, g_qkv);
    cudaGetSymbolAddress((void**)&y_ptr,   g_y);

    cudaFuncSetAttribute(gemm_tf32_bias,
                         cudaFuncAttributeMaxDynamicSharedMemorySize,
                         GEMM_SMEM_BYTES);
    cudaFuncSetAttribute(flash_attn_tc,
                         cudaFuncAttributeMaxDynamicSharedMemorySize,
                         FA_SMEM_BYTES);

    // 1) qkv = x @ W_attn + b_attn   [8192,1024]x[1024,3072]
    {
        dim3 grid(C3 / TBN, MROWS / TBM);
        gemm_tf32_bias<<<grid, 256, GEMM_SMEM_BYTES>>>(
            x, W_attn, b_attn, qkv_ptr, MROWS, C3, CDIM);
    }
    // 2) tensor-core flash attention -> g_y
    {
        dim3 grid(SEQ / FA_BM, NHEAD, BATCH);
        flash_attn_tc<<<grid, 128, FA_SMEM_BYTES>>>(qkv_ptr, y_ptr);
    }
    // 3) out = y @ W_proj + b_proj   [8192,1024]x[1024,1024]
    {
        dim3 grid(CDIM / TBN, MROWS / TBM);
        gemm_tf32_bias<<<grid, 256, GEMM_SMEM_BYTES>>>(
            y_ptr, W_proj, b_proj, out, MROWS, CDIM, CDIM);
    }
}